// round 12
// baseline (speedup 1.0000x reference)
#include <cuda_runtime.h>
#include <cuda_fp16.h>
#include <math.h>
#include <stdint.h>

#define BB 256
#define SS 512
#define HH 1024
#define WW 64
#define MROWS (BB*WW)        // 16384 score rows
#define AROWS (MROWS + BB)   // + 256 hc rows
#define NT 16                // N tiles of 64
#define BM 128
#define BN 64
#define BK 64                // fp16 K per stage (two 32-elt halves)
#define KITERS (HH/BK)       // 16 (mode 1)
#define KSPL 4               // K-split for u-GEMM
// Per half: A rows [a0 32fp16 | a1 32fp16] = 128B SW128; B rows 32fp16=64B, 2/128B row.
#define A_HALF 16384
#define B_HALF 4096
#define B_OFF (2*A_HALF)               // 32768
#define STAGE_BYTES (2*A_HALF + 2*B_HALF)  // 40960
#define NSTAGE 2
#define SMEM_ALLOC (NSTAGE*STAGE_BYTES)    // 81920

// ---------------- scratch ----------------
__device__ __half g_A0[(size_t)AROWS*HH];
__device__ __half g_A1[(size_t)AROWS*HH];
__device__ __half g_Wh[(size_t)HH*2*HH];
__device__ float g_u4[(size_t)KSPL*BB*HH];
__device__ float g_u[(size_t)BB*HH];
__device__ float g_part[NT*MROWS];

// ---------------- PTX helpers (no sm_103a-gated features) ----------------
__device__ __forceinline__ uint32_t smem_u32(const void* p) {
    uint32_t a;
    asm("{ .reg .u64 t; cvta.to.shared.u64 t, %1; cvt.u32.u64 %0, t; }" : "=r"(a) : "l"(p));
    return a;
}
__device__ __forceinline__ void cpasync16(uint32_t dst, const void* src) {
    asm volatile("cp.async.cg.shared.global [%0], [%1], 16;" :: "r"(dst), "l"(src) : "memory");
}
__device__ __forceinline__ void cp_commit() { asm volatile("cp.async.commit_group;" ::: "memory"); }
template <int N> __device__ __forceinline__ void cp_wait() {
    asm volatile("cp.async.wait_group %0;" :: "n"(N) : "memory");
}
#define LDSM4(r, addr) \
    asm volatile("ldmatrix.sync.aligned.m8n8.x4.shared.b16 {%0,%1,%2,%3}, [%4];" \
        : "=r"((r)[0]),"=r"((r)[1]),"=r"((r)[2]),"=r"((r)[3]) : "r"(addr))
#define MMA(d, a, b0, b1) \
    asm volatile("mma.sync.aligned.m16n8k16.row.col.f32.f16.f16.f32 " \
        "{%0,%1,%2,%3},{%4,%5,%6,%7},{%8,%9},{%0,%1,%2,%3};" \
        : "+f"((d)[0]),"+f"((d)[1]),"+f"((d)[2]),"+f"((d)[3]) \
        : "r"((a)[0]),"r"((a)[1]),"r"((a)[2]),"r"((a)[3]),"r"(b0),"r"(b1))

// ---------------- split helpers ----------------
__device__ __forceinline__ void split2h(float x, __half& a0, __half& a1) {
    a0 = __float2half_rn(x);
    a1 = __float2half_rn(x - __half2float(a0));
}

// ---------------- kernel: convert W to single fp16 plane ----------------
__global__ __launch_bounds__(256) void convert_w(const float* __restrict__ Wa) {
    size_t base = ((size_t)blockIdx.x * 256 + threadIdx.x) * 4;
    float4 x = *reinterpret_cast<const float4*>(Wa + base);
    reinterpret_cast<__half2*>(g_Wh + base)[0] = __floats2half2_rn(x.x, x.y);
    reinterpret_cast<__half2*>(g_Wh + base)[1] = __floats2half2_rn(x.z, x.w);
}

// ---------------- kernel: gather rows + 2-way fp16 split ----------------
__global__ __launch_bounds__(256) void gather_split_a(const float* __restrict__ inp,
                                                      const float* __restrict__ hc,
                                                      const int* __restrict__ slen) {
    int row = blockIdx.x;
    const float* src;
    if (row < MROWS) {
        int b = row >> 6, w = row & 63;
        src = inp + ((size_t)b * SS + (slen[b] - WW + w)) * HH;
    } else {
        src = hc + (size_t)(row - MROWS) * HH;
    }
    int i = threadIdx.x * 4;
    float4 x = *reinterpret_cast<const float4*>(src + i);
    float v4[4] = {x.x, x.y, x.z, x.w};
    __half s0[4], s1[4];
    #pragma unroll
    for (int k = 0; k < 4; k++) split2h(v4[k], s0[k], s1[k]);
    size_t base = (size_t)row * HH + i;
    #pragma unroll
    for (int k = 0; k < 2; k++) {
        reinterpret_cast<__half2*>(g_A0 + base)[k] = __halves2half2(s0[2*k], s0[2*k+1]);
        reinterpret_cast<__half2*>(g_A1 + base)[k] = __halves2half2(s1[2*k], s1[2*k+1]);
    }
}

// ---------------- kernel: reduce u partials + bias ----------------
__global__ __launch_bounds__(256) void reduce_u(const float* __restrict__ ba) {
    int i = blockIdx.x * 1024 + threadIdx.x * 4;
    float4 s = *reinterpret_cast<const float4*>(g_u4 + i);
    #pragma unroll
    for (int z = 1; z < KSPL; z++) {
        float4 p = *reinterpret_cast<const float4*>(g_u4 + (size_t)z * BB * HH + i);
        s.x += p.x; s.y += p.y; s.z += p.z; s.w += p.w;
    }
    int col = i & (HH - 1);
    float4 b4 = *reinterpret_cast<const float4*>(ba + col);
    s.x += b4.x; s.y += b4.y; s.z += b4.z; s.w += b4.w;
    *reinterpret_cast<float4*>(g_u + i) = s;
}

// ---------------- HMMA GEMM: fp32 emulated via 2 fp16 products ----------------
// a = a0 + a1 (fp16 split); b single fp16. E = A0*B + A1*B.
// BM=128/BN=64 tile (fine-grained grid: 2048 blocks -> ~1% wave waste).
// BK=64 (two 32-elt halves), 2-stage pipeline, single barrier per iter.
// A fragments preloaded for both ks per half; B LDSM double-buffered.
// mode 0: K-split partial u (blockIdx.z = kz) -> g_u4
// mode 1: full K scores -> g_part
__global__ __launch_bounds__(256, 2) void gemm_hmma(int mode, int arow_base, int kofs,
                                                    int niter,
                                                    const float* __restrict__ vv) {
    extern __shared__ __align__(1024) char smem_raw[];
    const uint32_t sbase = smem_u32(smem_raw);
    __shared__ float srow[2][BM];

    const int tid = threadIdx.x;
    const int lane = tid & 31;
    const int wid = tid >> 5;
    const int wm = (wid & 3) * 32;     // warp M offset (4 M-warps)
    const int wn = (wid >> 2) * 32;    // warp N offset (2 N-warps)
    const int n0 = blockIdx.x * BN;
    const int m0 = blockIdx.y * BM;
    const int kbase = blockIdx.z * (HH / KSPL);   // 0 for mode 1 (gridDim.z==1)

    // ---- A fill: 4 chunks/thread per half (rows fr0 + j*32) ----
    const int fp = (tid >> 2) & 1;     // plane
    const int fkc = tid & 3;           // 16B chunk within 32-elt half
    const int fr0 = tid >> 3;
    const __half* fbaseA = (fp ? g_A1 : g_A0)
        + (size_t)(arow_base + m0 + fr0) * HH + kbase + fkc * 8;
    const uint32_t fdstA = fr0 * 128 + (((tid & 7) * 16) ^ ((fr0 & 7) << 4));
    // ---- B fill: 1 chunk/thread per half (64 logical rows) ----
    const int rb0 = tid >> 2;          // logical B row 0..63
    const __half* fbaseB = g_Wh + (size_t)(n0 + rb0) * (2 * HH) + kofs + kbase + fkc * 8;
    uint32_t fdstB;
    {
        int q = rb0 >> 1;
        fdstB = B_OFF + q * 128 + ((((rb0 & 1) * 64) + fkc * 16) ^ ((q & 7) << 4));
    }

    auto fill = [&](int s, int k0) {
        uint32_t stg = sbase + s * STAGE_BYTES;
        #pragma unroll
        for (int h = 0; h < 2; h++) {
            #pragma unroll
            for (int j = 0; j < 4; j++)
                cpasync16(stg + fdstA + h * A_HALF + j * 4096,
                          fbaseA + (size_t)j * 32 * HH + k0 + h * 32);
            cpasync16(stg + fdstB + h * B_HALF, fbaseB + k0 + h * 32);
        }
    };

    float acc[2][4][4] = {};
    // ---- LDSM bases + swizzled constants (per 32-elt half) ----
    const uint32_t lrow = lane & 15;
    const uint32_t hi16 = (lane >> 4) * 16;
    const uint32_t swm = (lrow & 7) << 4;
    uint32_t cswA[2][2];   // [plane][ks]
    #pragma unroll
    for (int p = 0; p < 2; p++)
        #pragma unroll
        for (int ks = 0; ks < 2; ks++)
            cswA[p][ks] = ((uint32_t)(p * 64 + ks * 32) + hi16) ^ swm;
    const uint32_t aBase = sbase + (wm + lrow) * 128;
    const uint32_t wnl = wn + lrow;
    const uint32_t q0 = wnl >> 1;
    uint32_t cswB[2];      // [ks]
    #pragma unroll
    for (int ks = 0; ks < 2; ks++)
        cswB[ks] = (((wnl & 1) * 64) + (uint32_t)(ks * 32) + hi16) ^ ((q0 & 7) << 4);
    const uint32_t bBase = sbase + B_OFF + q0 * 128;

    fill(0, 0);
    cp_commit();

    for (int it = 0; it < niter; ++it) {
        cp_wait<0>();          // fill(it) complete
        __syncthreads();       // publish fill(it); all warps done with other stage
        if (it + 1 < niter) {
            fill((it + 1) & 1, (it + 1) * BK);
            cp_commit();
        }

        const uint32_t soff = (uint32_t)(it & 1) * STAGE_BYTES;

        #pragma unroll
        for (int h = 0; h < 2; h++) {
            const uint32_t aAddr = aBase + soff + h * A_HALF;
            const uint32_t bAddr = bBase + soff + h * B_HALF;

            // preload A fragments for both ks halves (8 LDSMs, 32 regs)
            uint32_t a0f[2][2][4], a1f[2][2][4];   // [ks][mi][4]
            #pragma unroll
            for (int ks = 0; ks < 2; ks++)
                #pragma unroll
                for (int mi = 0; mi < 2; mi++) {
                    LDSM4(a0f[ks][mi], aAddr + mi * 2048 + cswA[0][ks]);
                    LDSM4(a1f[ks][mi], aAddr + mi * 2048 + cswA[1][ks]);
                }

            // 4 B-units: u = ks*2 + n2, double-buffered one ahead
            uint32_t bq[2][4];
            LDSM4(bq[0], bAddr + cswB[0]);
            #pragma unroll
            for (int u = 0; u < 4; u++) {
                const int ks = u >> 1, n2 = u & 1;
                if (u + 1 < 4) {
                    const int v = u + 1;
                    LDSM4(bq[v & 1], bAddr + (v & 1) * 1024 + cswB[v >> 1]);
                }
                const uint32_t* bc = bq[u & 1];
                #pragma unroll
                for (int mi = 0; mi < 2; mi++) {
                    MMA(acc[mi][2*n2],   a0f[ks][mi], bc[0], bc[2]);
                    MMA(acc[mi][2*n2+1], a0f[ks][mi], bc[1], bc[3]);
                    MMA(acc[mi][2*n2],   a1f[ks][mi], bc[0], bc[2]);
                    MMA(acc[mi][2*n2+1], a1f[ks][mi], bc[1], bc[3]);
                }
            }
        }
    }

    const int quad = lane >> 2, qt = lane & 3;

    if (mode == 1) {
        // epilogue: s_row = sum_n v[n]*tanh(E + u[b,n])
        const int b_warp = (m0 + wm) >> 6;
        const float* up = g_u + (size_t)b_warp * HH + n0 + wn;
        const float* vp = vv + n0 + wn;
        float rs[4] = {0.f, 0.f, 0.f, 0.f};
        #pragma unroll
        for (int mi = 0; mi < 2; mi++)
            #pragma unroll
            for (int ni = 0; ni < 4; ni++)
                #pragma unroll
                for (int r = 0; r < 4; r++) {
                    int col = ni * 8 + qt * 2 + (r & 1);
                    float e = acc[mi][ni][r] + __ldg(up + col);
                    rs[mi * 2 + (r >> 1)] += __ldg(vp + col) * tanhf(e);
                }
        #pragma unroll
        for (int i = 0; i < 4; i++) {
            rs[i] += __shfl_xor_sync(0xffffffffu, rs[i], 1);
            rs[i] += __shfl_xor_sync(0xffffffffu, rs[i], 2);
        }
        __syncthreads();
        if (qt == 0) {
            #pragma unroll
            for (int mi = 0; mi < 2; mi++)
                #pragma unroll
                for (int hf = 0; hf < 2; hf++)
                    srow[wid >> 2][wm + mi * 16 + hf * 8 + quad] = rs[mi * 2 + hf];
        }
        __syncthreads();
        if (tid < BM)
            g_part[blockIdx.x * MROWS + m0 + tid] = srow[0][tid] + srow[1][tid];
    } else {
        // partial u (no bias; reduce_u adds it)
        float* uo = g_u4 + (size_t)blockIdx.z * BB * HH;
        #pragma unroll
        for (int mi = 0; mi < 2; mi++)
            #pragma unroll
            for (int ni = 0; ni < 4; ni++)
                #pragma unroll
                for (int r = 0; r < 4; r++) {
                    int row = m0 + wm + mi * 16 + (r >> 1) * 8 + quad;
                    int col = n0 + wn + ni * 8 + qt * 2 + (r & 1);
                    uo[(size_t)row * HH + col] = acc[mi][ni][r];
                }
    }
}

// ---------------- finalize: softmax + context + parent ----------------
// grid (BB, 4): block y covers 256 h-columns
__global__ __launch_bounds__(256) void finalize(const float* __restrict__ inp,
                                                const int* __restrict__ slen,
                                                const int* __restrict__ parent,
                                                float* __restrict__ out) {
    const int b = blockIdx.x;
    const int h0 = blockIdx.y * 256;
    const int tid = threadIdx.x;
    __shared__ float ssc[WW];
    __shared__ float sattn[WW];
    const int len = slen[b];

    if (tid < WW) {
        float s = 0.f;
        #pragma unroll
        for (int t = 0; t < NT; t++) s += g_part[t * MROWS + b * WW + tid];
        ssc[tid] = s;
    }
    __syncthreads();

    float mx = -1e30f;
    #pragma unroll 8
    for (int w = 0; w < WW; w++) mx = fmaxf(mx, ssc[w]);
    float sum = 0.f;
    #pragma unroll 8
    for (int w = 0; w < WW; w++) sum += expf(ssc[w] - mx);
    float inv = 1.f / sum;

    if (tid < WW) {
        float a = expf(ssc[tid] - mx) * inv;
        if (blockIdx.y == 0) out[b * WW + tid] = a;
        sattn[tid] = a;
    }
    __syncthreads();

    const float* base = inp + (size_t)b * SS * HH;
    const int off0 = (len - WW) * HH;
    {
        int h = h0 + tid;
        float acc = 0.f;
        #pragma unroll 8
        for (int w = 0; w < WW; w++)
            acc = fmaf(sattn[w], base[off0 + w * HH + h], acc);
        out[MROWS + b * HH + h] = acc;
        const int poff = (len - parent[b] - 1) * HH;
        out[MROWS + BB * HH + b * HH + h] = base[poff + h];
    }
}

// ---------------------------------------------------------------------------
extern "C" void kernel_launch(void* const* d_in, const int* in_sizes, int n_in,
                              void* d_out, int out_size) {
    const float* inp    = (const float*)d_in[0];
    const float* hc     = (const float*)d_in[1];
    const float* Wa     = (const float*)d_in[2];
    const float* ba     = (const float*)d_in[3];
    const float* v      = (const float*)d_in[4];
    const int*   slen   = (const int*)d_in[5];
    const int*   parent = (const int*)d_in[6];
    float* out = (float*)d_out;

    static int configured = 0;
    if (!configured) {
        cudaFuncSetAttribute(gemm_hmma, cudaFuncAttributeMaxDynamicSharedMemorySize, SMEM_ALLOC);
        configured = 1;
    }

    convert_w<<<(HH * 2 * HH) / 1024, 256>>>(Wa);
    gather_split_a<<<AROWS, 256>>>(inp, hc, slen);
    // u partials: K-split x4, 4 iters each
    gemm_hmma<<<dim3(NT, BB / BM, KSPL), 256, SMEM_ALLOC>>>(0, MROWS, 0, KITERS / KSPL, v);
    reduce_u<<<(BB * HH) / 1024, 256>>>(ba);
    // scores: full K
    gemm_hmma<<<dim3(NT, MROWS / BM, 1), 256, SMEM_ALLOC>>>(1, 0, HH, KITERS, v);
    finalize<<<dim3(BB, 4), 256>>>(inp, slen, parent, out);
}

// round 13
// speedup vs baseline: 1.1033x; 1.1033x over previous
#include <cuda_runtime.h>
#include <cuda_fp16.h>
#include <math.h>
#include <stdint.h>

#define BB 256
#define SS 512
#define HH 1024
#define WW 64
#define MROWS (BB*WW)        // 16384 score rows
#define AROWS (MROWS + BB)   // + 256 hc rows
#define NT 8                 // N tiles of 128
#define BM 128
#define BN 128
#define BK 64                // fp16 K per stage (two 32-elt halves)
#define KITERS (HH/BK)       // 16 (mode 1)
#define KSPL 4               // K-split for u-GEMM
// Per half: A rows [a0 32fp16 | a1 32fp16] = 128B SW128; B rows 32fp16=64B, 2/128B row.
#define A_HALF 16384
#define B_HALF 8192
#define B_OFF (2*A_HALF)               // 32768
#define STAGE_BYTES (2*A_HALF + 2*B_HALF)  // 49152
#define NSTAGE 2
#define SMEM_ALLOC (NSTAGE*STAGE_BYTES)    // 98304

// ---------------- scratch ----------------
__device__ __half g_A0[(size_t)AROWS*HH];
__device__ __half g_A1[(size_t)AROWS*HH];
__device__ __half g_Wh[(size_t)HH*2*HH];
__device__ float g_u4[(size_t)KSPL*BB*HH];
__device__ float g_u[(size_t)BB*HH];
__device__ float g_part[NT*MROWS];

// ---------------- PTX helpers (no sm_103a-gated features) ----------------
__device__ __forceinline__ uint32_t smem_u32(const void* p) {
    uint32_t a;
    asm("{ .reg .u64 t; cvta.to.shared.u64 t, %1; cvt.u32.u64 %0, t; }" : "=r"(a) : "l"(p));
    return a;
}
__device__ __forceinline__ void cpasync16(uint32_t dst, const void* src) {
    asm volatile("cp.async.cg.shared.global [%0], [%1], 16;" :: "r"(dst), "l"(src) : "memory");
}
__device__ __forceinline__ void cp_commit() { asm volatile("cp.async.commit_group;" ::: "memory"); }
template <int N> __device__ __forceinline__ void cp_wait() {
    asm volatile("cp.async.wait_group %0;" :: "n"(N) : "memory");
}
#define LDSM4(r, addr) \
    asm volatile("ldmatrix.sync.aligned.m8n8.x4.shared.b16 {%0,%1,%2,%3}, [%4];" \
        : "=r"((r)[0]),"=r"((r)[1]),"=r"((r)[2]),"=r"((r)[3]) : "r"(addr))
#define MMA(d, a, b0, b1) \
    asm volatile("mma.sync.aligned.m16n8k16.row.col.f32.f16.f16.f32 " \
        "{%0,%1,%2,%3},{%4,%5,%6,%7},{%8,%9},{%0,%1,%2,%3};" \
        : "+f"((d)[0]),"+f"((d)[1]),"+f"((d)[2]),"+f"((d)[3]) \
        : "r"((a)[0]),"r"((a)[1]),"r"((a)[2]),"r"((a)[3]),"r"(b0),"r"(b1))

// ---------------- split helpers ----------------
__device__ __forceinline__ void split2h(float x, __half& a0, __half& a1) {
    a0 = __float2half_rn(x);
    a1 = __float2half_rn(x - __half2float(a0));
}

// ---------------- kernel: convert W to single fp16 plane (8 floats/thread) ----
__global__ __launch_bounds__(256) void convert_w(const float* __restrict__ Wa) {
    size_t base = ((size_t)blockIdx.x * 256 + threadIdx.x) * 8;
    #pragma unroll
    for (int q = 0; q < 2; q++) {
        float4 x = *reinterpret_cast<const float4*>(Wa + base + q * 4);
        reinterpret_cast<__half2*>(g_Wh + base + q * 4)[0] = __floats2half2_rn(x.x, x.y);
        reinterpret_cast<__half2*>(g_Wh + base + q * 4)[1] = __floats2half2_rn(x.z, x.w);
    }
}

// ---------------- kernel: gather rows + 2-way fp16 split ----------------
// row = row_base + blockIdx.x
__global__ __launch_bounds__(256) void gather_split_a(const float* __restrict__ inp,
                                                      const float* __restrict__ hc,
                                                      const int* __restrict__ slen,
                                                      int row_base) {
    int row = row_base + blockIdx.x;
    const float* src;
    if (row < MROWS) {
        int b = row >> 6, w = row & 63;
        src = inp + ((size_t)b * SS + (slen[b] - WW + w)) * HH;
    } else {
        src = hc + (size_t)(row - MROWS) * HH;
    }
    int i = threadIdx.x * 4;
    float4 x = *reinterpret_cast<const float4*>(src + i);
    float v4[4] = {x.x, x.y, x.z, x.w};
    __half s0[4], s1[4];
    #pragma unroll
    for (int k = 0; k < 4; k++) split2h(v4[k], s0[k], s1[k]);
    size_t base = (size_t)row * HH + i;
    #pragma unroll
    for (int k = 0; k < 2; k++) {
        reinterpret_cast<__half2*>(g_A0 + base)[k] = __halves2half2(s0[2*k], s0[2*k+1]);
        reinterpret_cast<__half2*>(g_A1 + base)[k] = __halves2half2(s1[2*k], s1[2*k+1]);
    }
}

// ---------------- kernel: reduce u partials + bias ----------------
__global__ __launch_bounds__(256) void reduce_u(const float* __restrict__ ba) {
    int i = blockIdx.x * 1024 + threadIdx.x * 4;
    float4 s = *reinterpret_cast<const float4*>(g_u4 + i);
    #pragma unroll
    for (int z = 1; z < KSPL; z++) {
        float4 p = *reinterpret_cast<const float4*>(g_u4 + (size_t)z * BB * HH + i);
        s.x += p.x; s.y += p.y; s.z += p.z; s.w += p.w;
    }
    int col = i & (HH - 1);
    float4 b4 = *reinterpret_cast<const float4*>(ba + col);
    s.x += b4.x; s.y += b4.y; s.z += b4.z; s.w += b4.w;
    *reinterpret_cast<float4*>(g_u + i) = s;
}

// ---------------- HMMA GEMM: fp32 emulated via 2 fp16 products ----------------
// a = a0 + a1 (fp16 split); b single fp16. E = A0*B + A1*B.
// BK=64 (two 32-elt halves), 2-stage pipeline, single barrier per iter.
// mode 0: K-split partial u (blockIdx.z = kz) -> g_u4
// mode 1: full K scores -> g_part
__global__ __launch_bounds__(256, 2) void gemm_hmma(int mode, int arow_base, int kofs,
                                                    int niter,
                                                    const float* __restrict__ vv) {
    extern __shared__ __align__(1024) char smem_raw[];
    const uint32_t sbase = smem_u32(smem_raw);
    __shared__ float srow[2][BM];

    const int tid = threadIdx.x;
    const int lane = tid & 31;
    const int wid = tid >> 5;
    const int wm = (wid & 3) * 32;     // warp M offset
    const int wn = (wid >> 2) * 64;    // warp N offset
    const int n0 = blockIdx.x * BN;
    const int m0 = blockIdx.y * BM;
    const int kbase = blockIdx.z * (HH / KSPL);   // 0 for mode 1 (gridDim.z==1)

    // ---- A fill: 4 chunks/thread per half (rows fr0 + j*32) ----
    const int fp = (tid >> 2) & 1;     // plane
    const int fkc = tid & 3;           // 16B chunk within 32-elt half
    const int fr0 = tid >> 3;
    const __half* fbaseA = (fp ? g_A1 : g_A0)
        + (size_t)(arow_base + m0 + fr0) * HH + kbase + fkc * 8;
    const uint32_t fdstA = fr0 * 128 + (((tid & 7) * 16) ^ ((fr0 & 7) << 4));
    // ---- B fill: 2 chunks/thread per half (rows rb0, rb0+64) ----
    const int rb0 = tid >> 2;
    const __half* fbaseB0 = g_Wh + (size_t)(n0 + rb0) * (2 * HH) + kofs + kbase + fkc * 8;
    const __half* fbaseB1 = g_Wh + (size_t)(n0 + rb0 + 64) * (2 * HH) + kofs + kbase + fkc * 8;
    uint32_t fdstB0, fdstB1;
    {
        int q = rb0 >> 1;
        fdstB0 = B_OFF + q * 128 + ((((rb0 & 1) * 64) + fkc * 16) ^ ((q & 7) << 4));
        int r1 = rb0 + 64, q1 = r1 >> 1;
        fdstB1 = B_OFF + q1 * 128 + ((((r1 & 1) * 64) + fkc * 16) ^ ((q1 & 7) << 4));
    }

    auto fill = [&](int s, int k0) {
        uint32_t stg = sbase + s * STAGE_BYTES;
        #pragma unroll
        for (int h = 0; h < 2; h++) {
            #pragma unroll
            for (int j = 0; j < 4; j++)
                cpasync16(stg + fdstA + h * A_HALF + j * 4096,
                          fbaseA + (size_t)j * 32 * HH + k0 + h * 32);
            cpasync16(stg + fdstB0 + h * B_HALF, fbaseB0 + k0 + h * 32);
            cpasync16(stg + fdstB1 + h * B_HALF, fbaseB1 + k0 + h * 32);
        }
    };

    float acc[2][8][4] = {};
    // ---- LDSM bases + swizzled constants (per 32-elt half) ----
    const uint32_t lrow = lane & 15;
    const uint32_t hi16 = (lane >> 4) * 16;
    const uint32_t swm = (lrow & 7) << 4;
    uint32_t cswA[2][2];   // [plane][ks]
    #pragma unroll
    for (int p = 0; p < 2; p++)
        #pragma unroll
        for (int ks = 0; ks < 2; ks++)
            cswA[p][ks] = ((uint32_t)(p * 64 + ks * 32) + hi16) ^ swm;
    const uint32_t aBase = sbase + (wm + lrow) * 128;
    const uint32_t wnl = wn + lrow;
    const uint32_t q0 = wnl >> 1;
    uint32_t cswB[2];      // [ks]
    #pragma unroll
    for (int ks = 0; ks < 2; ks++)
        cswB[ks] = (((wnl & 1) * 64) + (uint32_t)(ks * 32) + hi16) ^ ((q0 & 7) << 4);
    const uint32_t bBase = sbase + B_OFF + q0 * 128;

    fill(0, 0);
    cp_commit();

    for (int it = 0; it < niter; ++it) {
        cp_wait<0>();          // fill(it) complete
        __syncthreads();       // publish fill(it); all warps done with other stage
        if (it + 1 < niter) {
            fill((it + 1) & 1, (it + 1) * BK);
            cp_commit();
        }

        const uint32_t soff = (uint32_t)(it & 1) * STAGE_BYTES;

        #pragma unroll
        for (int h = 0; h < 2; h++) {
            const uint32_t aAddr = aBase + soff + h * A_HALF;
            const uint32_t bAddr = bBase + soff + h * B_HALF;

            uint32_t a0f[2][4], a1f[2][4];
            uint32_t bq[2][4];
            LDSM4(bq[0], bAddr + cswB[0]);

            #pragma unroll
            for (int u = 0; u < 8; u++) {
                const int ks = u >> 2, n2 = u & 3;
                if ((u & 3) == 0) {
                    #pragma unroll
                    for (int mi = 0; mi < 2; mi++) {
                        LDSM4(a0f[mi], aAddr + mi * 2048 + cswA[0][ks]);
                        LDSM4(a1f[mi], aAddr + mi * 2048 + cswA[1][ks]);
                    }
                }
                if (u + 1 < 8) {
                    const int v = u + 1;
                    LDSM4(bq[v & 1], bAddr + (v & 3) * 1024 + cswB[v >> 2]);
                }
                const uint32_t* bc = bq[u & 1];
                #pragma unroll
                for (int mi = 0; mi < 2; mi++) {
                    MMA(acc[mi][2*n2],   a0f[mi], bc[0], bc[2]);
                    MMA(acc[mi][2*n2+1], a0f[mi], bc[1], bc[3]);
                    MMA(acc[mi][2*n2],   a1f[mi], bc[0], bc[2]);
                    MMA(acc[mi][2*n2+1], a1f[mi], bc[1], bc[3]);
                }
            }
        }
    }

    const int quad = lane >> 2, qt = lane & 3;

    if (mode == 1) {
        // epilogue: s_row = sum_n v[n]*tanh(E + u[b,n])
        const int b_warp = (m0 + wm) >> 6;
        const float* up = g_u + (size_t)b_warp * HH + n0 + wn;
        const float* vp = vv + n0 + wn;
        float rs[4] = {0.f, 0.f, 0.f, 0.f};
        #pragma unroll
        for (int mi = 0; mi < 2; mi++)
            #pragma unroll
            for (int ni = 0; ni < 8; ni++)
                #pragma unroll
                for (int r = 0; r < 4; r++) {
                    int col = ni * 8 + qt * 2 + (r & 1);
                    float e = acc[mi][ni][r] + __ldg(up + col);
                    rs[mi * 2 + (r >> 1)] += __ldg(vp + col) * tanhf(e);
                }
        #pragma unroll
        for (int i = 0; i < 4; i++) {
            rs[i] += __shfl_xor_sync(0xffffffffu, rs[i], 1);
            rs[i] += __shfl_xor_sync(0xffffffffu, rs[i], 2);
        }
        __syncthreads();
        if (qt == 0) {
            #pragma unroll
            for (int mi = 0; mi < 2; mi++)
                #pragma unroll
                for (int hf = 0; hf < 2; hf++)
                    srow[wid >> 2][wm + mi * 16 + hf * 8 + quad] = rs[mi * 2 + hf];
        }
        __syncthreads();
        if (tid < BM)
            g_part[blockIdx.x * MROWS + m0 + tid] = srow[0][tid] + srow[1][tid];
    } else {
        // partial u (no bias; reduce_u adds it)
        float* uo = g_u4 + (size_t)blockIdx.z * BB * HH;
        #pragma unroll
        for (int mi = 0; mi < 2; mi++)
            #pragma unroll
            for (int ni = 0; ni < 8; ni++)
                #pragma unroll
                for (int r = 0; r < 4; r++) {
                    int row = m0 + wm + mi * 16 + (r >> 1) * 8 + quad;
                    int col = n0 + wn + ni * 8 + qt * 2 + (r & 1);
                    uo[(size_t)row * HH + col] = acc[mi][ni][r];
                }
    }
}

// ---------------- finalize: softmax + context + parent ----------------
// grid (BB, 4): block y covers 256 h-columns
__global__ __launch_bounds__(256) void finalize(const float* __restrict__ inp,
                                                const int* __restrict__ slen,
                                                const int* __restrict__ parent,
                                                float* __restrict__ out) {
    const int b = blockIdx.x;
    const int h0 = blockIdx.y * 256;
    const int tid = threadIdx.x;
    __shared__ float ssc[WW];
    __shared__ float sattn[WW];
    const int len = slen[b];

    if (tid < WW) {
        float s = 0.f;
        #pragma unroll
        for (int t = 0; t < NT; t++) s += g_part[t * MROWS + b * WW + tid];
        ssc[tid] = s;
    }
    __syncthreads();

    float mx = -1e30f;
    #pragma unroll 8
    for (int w = 0; w < WW; w++) mx = fmaxf(mx, ssc[w]);
    float sum = 0.f;
    #pragma unroll 8
    for (int w = 0; w < WW; w++) sum += expf(ssc[w] - mx);
    float inv = 1.f / sum;

    if (tid < WW) {
        float a = expf(ssc[tid] - mx) * inv;
        if (blockIdx.y == 0) out[b * WW + tid] = a;
        sattn[tid] = a;
    }
    __syncthreads();

    const float* base = inp + (size_t)b * SS * HH;
    const int off0 = (len - WW) * HH;
    {
        int h = h0 + tid;
        float acc = 0.f;
        #pragma unroll 8
        for (int w = 0; w < WW; w++)
            acc = fmaf(sattn[w], base[off0 + w * HH + h], acc);
        out[MROWS + b * HH + h] = acc;
        const int poff = (len - parent[b] - 1) * HH;
        out[MROWS + BB * HH + b * HH + h] = base[poff + h];
    }
}

// ---------------------------------------------------------------------------
extern "C" void kernel_launch(void* const* d_in, const int* in_sizes, int n_in,
                              void* d_out, int out_size) {
    const float* inp    = (const float*)d_in[0];
    const float* hc     = (const float*)d_in[1];
    const float* Wa     = (const float*)d_in[2];
    const float* ba     = (const float*)d_in[3];
    const float* v      = (const float*)d_in[4];
    const int*   slen   = (const int*)d_in[5];
    const int*   parent = (const int*)d_in[6];
    float* out = (float*)d_out;

    static cudaStream_t s2 = nullptr;
    static cudaEvent_t eFork = nullptr, eJoin = nullptr;
    static int configured = 0;
    if (!configured) {
        cudaFuncSetAttribute(gemm_hmma, cudaFuncAttributeMaxDynamicSharedMemorySize, SMEM_ALLOC);
        cudaStreamCreateWithFlags(&s2, cudaStreamNonBlocking);
        cudaEventCreateWithFlags(&eFork, cudaEventDisableTiming);
        cudaEventCreateWithFlags(&eJoin, cudaEventDisableTiming);
        configured = 1;
    }

    cudaStream_t s0 = 0;   // capture stream (legacy default)

    // fork: u-chain (convert_w -> gather_hc -> gemm0 -> reduce_u) on s2,
    //       Mt gather on s0, concurrently.
    cudaEventRecord(eFork, s0);
    cudaStreamWaitEvent(s2, eFork, 0);

    convert_w<<<(HH * 2 * HH) / 2048, 256, 0, s2>>>(Wa);
    gather_split_a<<<BB, 256, 0, s2>>>(inp, hc, slen, MROWS);          // hc rows
    gemm_hmma<<<dim3(NT, BB / BM, KSPL), 256, SMEM_ALLOC, s2>>>(0, MROWS, 0, KITERS / KSPL, v);
    reduce_u<<<(BB * HH) / 1024, 256, 0, s2>>>(ba);

    gather_split_a<<<MROWS, 256, 0, s0>>>(inp, hc, slen, 0);           // Mt rows

    // join: gemm1 needs Mt gather (s0) + Wh/g_u (s2)
    cudaEventRecord(eJoin, s2);
    cudaStreamWaitEvent(s0, eJoin, 0);

    gemm_hmma<<<dim3(NT, MROWS / BM, 1), 256, SMEM_ALLOC, s0>>>(1, 0, HH, KITERS, v);
    finalize<<<dim3(BB, 4), 256, 0, s0>>>(inp, slen, parent, out);
}